// round 7
// baseline (speedup 1.0000x reference)
#include <cuda_runtime.h>

#define FEAT 32
#define RES_H 512
#define RES_W 128
#define HW (RES_H * RES_W)
#define PLANE_ELEMS (FEAT * HW)
#define TIME_STEP_F 0.00390625f   /* 1/(2*128), exact in fp32 */
#define INV_BOUNDS_F 0.625f       /* fp32(1/fp32(1.6)) == 0.625 exactly (XLA folds /1.6 -> *0.625) */
#define PPW 32                    /* points per warp */

// 3 transposed planes, layout [H][W][F]: 32 features contiguous (one 128B line).
__device__ __align__(256) float g_tp[3][PLANE_ELEMS];

// Packed f32 pair multiply (sm_103a) — IEEE rn per element, bit-identical to
// two scalar __fmul_rn.
__device__ __forceinline__ unsigned long long mul2(unsigned long long a,
                                                   unsigned long long b) {
    unsigned long long r;
    asm("mul.rn.f32x2 %0, %1, %2;" : "=l"(r) : "l"(a), "l"(b));
    return r;
}

// ---------------------------------------------------------------------------
// Pre-pass: transpose [F=32, HW] -> [HW, F]. 256 hw x 32 f tiles, float4 both
// global sides, MLP=8.
// ---------------------------------------------------------------------------
__global__ void transpose_planes(const float* __restrict__ p0,
                                 const float* __restrict__ p1,
                                 const float* __restrict__ p2) {
    __shared__ float tile[256][33];
    const int plane = blockIdx.y;
    const float* __restrict__ src = (plane == 0) ? p0 : ((plane == 1) ? p1 : p2);
    float* __restrict__ dst = g_tp[plane];

    const int hw0 = blockIdx.x * 256;
    const int tid = threadIdx.x;

    #pragma unroll
    for (int k = 0; k < 8; k++) {
        const int lin = tid + 256 * k;
        const int f  = lin >> 6;
        const int vc = lin & 63;
        const float4 v = *(const float4*)&src[f * HW + hw0 + vc * 4];
        tile[vc * 4 + 0][f] = v.x;
        tile[vc * 4 + 1][f] = v.y;
        tile[vc * 4 + 2][f] = v.z;
        tile[vc * 4 + 3][f] = v.w;
    }
    __syncthreads();
    #pragma unroll
    for (int k = 0; k < 8; k++) {
        const int lin = tid + 256 * k;
        const int r  = lin >> 3;
        const int fc = lin & 7;
        float4 w;
        w.x = tile[r][fc * 4 + 0];
        w.y = tile[r][fc * 4 + 1];
        w.z = tile[r][fc * 4 + 2];
        w.w = tile[r][fc * 4 + 3];
        *(float4*)&dst[(hw0 + r) * FEAT + fc * 4] = w;
    }
}

// ---------------------------------------------------------------------------
// Index math — XLA-folded forms, round half-to-even, clamp. No FMA contraction.
// ---------------------------------------------------------------------------
__device__ __forceinline__ int idx_w(float c) {
    float v = __fmul_rn(__fadd_rn(c, 1.0f), 63.5f);     // 0.5*(128-1) folded
    int k = (int)rintf(v);
    return min(max(k, 0), RES_W - 1);
}
__device__ __forceinline__ int idx_h(float c) {
    float v = __fmul_rn(__fadd_rn(c, 1.0f), 255.5f);    // 0.5*(512-1) folded
    int k = (int)rintf(v);
    return min(max(k, 0), RES_H - 1);
}

// ---------------------------------------------------------------------------
// Main kernel: warp handles PPW=32 points.
// Phase 1: every lane computes the 3 plane base offsets of one point.
// Phase 2 (fast path): 2 batches x 4 quad-iterations. Each batch front-issues
//   ALL 12 gather LDG.128 (MLP=12 per warp), then multiplies + streams 8
//   STG.128. Tail warp takes a guarded scalar path. Point n-1 handled by
//   warp 0's fused fixup (disjoint rows -> race-free).
// ---------------------------------------------------------------------------
__global__ void __launch_bounds__(256)
displacement_kernel(const float* __restrict__ pts,
                    const float* __restrict__ tim,
                    float* __restrict__ out,
                    int n) {
    const int warp_id = blockIdx.x * (blockDim.x >> 5) + (threadIdx.x >> 5);
    const int lane = threadIdx.x & 31;
    const long long nb = (long long)n * FEAT;

    // ---- Fused last-point fixup (warp 0 only; writes rows for i = n-1) ----
    if (warp_id == 0) {
        const int i = n - 1;
        const float t  = __fadd_rn(__fmul_rn(tim[i], 2.0f), -1.0f);
        const float p0 = __fmul_rn(-pts[3 * i + 0], INV_BOUNDS_F);
        const float p1 = __fmul_rn(-pts[3 * i + 1], INV_BOUNDS_F);
        const float p2 = __fmul_rn(-pts[3 * i + 2], INV_BOUNDS_F);
        const int ix = idx_w(t);
        const float fo = __fmul_rn(__fmul_rn(
            __ldg(&g_tp[0][(idx_h(p0) * RES_W + ix) * FEAT + lane]),
            __ldg(&g_tp[1][(idx_h(p1) * RES_W + ix) * FEAT + lane])),
            __ldg(&g_tp[2][(idx_h(p2) * RES_W + ix) * FEAT + lane]));
        // data.at[-1].add(-TIME_STEP): all 4 coords of the last row shift.
        const float ts = __fadd_rn(t,  -TIME_STEP_F);
        const float q0 = __fadd_rn(p0, -TIME_STEP_F);
        const float q1 = __fadd_rn(p1, -TIME_STEP_F);
        const float q2 = __fadd_rn(p2, -TIME_STEP_F);
        const int ixs = idx_w(ts);
        const float fs = __fmul_rn(__fmul_rn(
            __ldg(&g_tp[0][(idx_h(q0) * RES_W + ixs) * FEAT + lane]),
            __ldg(&g_tp[1][(idx_h(q1) * RES_W + ixs) * FEAT + lane])),
            __ldg(&g_tp[2][(idx_h(q2) * RES_W + ixs) * FEAT + lane]));
        const bool cond = __fadd_rn(p0, TIME_STEP_F) > 1.0f;
        out[(long long)i * FEAT + lane]      = cond ? fs : fo;   // feature_A
        out[nb + (long long)i * FEAT + lane] = cond ? fo : fs;   // feature_B
    }

    const int base = warp_id * PPW;
    if (base >= n) return;

    // Phase 1: one point per lane.
    int b0 = 0, b1 = 0, b2 = 0;
    const int li = base + lane;
    if (li < n) {
        const float t  = __fadd_rn(__fmul_rn(tim[li], 2.0f), -1.0f);
        const float p0 = __fmul_rn(-pts[3 * li + 0], INV_BOUNDS_F);
        const float p1 = __fmul_rn(-pts[3 * li + 1], INV_BOUNDS_F);
        const float p2 = __fmul_rn(-pts[3 * li + 2], INV_BOUNDS_F);
        const int ix = idx_w(t);
        b0 = (idx_h(p0) * RES_W + ix) * FEAT;
        b1 = (idx_h(p1) * RES_W + ix) * FEAT;
        b2 = (idx_h(p2) * RES_W + ix) * FEAT;
    }

    const int g  = lane >> 3;          // point within quad
    const int fe = (lane & 7) * 4;     // feature chunk
    const int n_main = n - 1;          // point n-1 handled by fixup

    if (base + PPW <= n_main) {
        // ---- Fast path: no bounds checks; 2 pipelined batches of 4 quads ----
        #pragma unroll
        for (int jj = 0; jj < 2; jj++) {
            ulonglong2 a[4], b[4], c[4];
            long long ob[4];
            // Front-batch 12 independent gathers (MLP = 12).
            #pragma unroll
            for (int k = 0; k < 4; k++) {
                const int src = (jj * 4 + k) * 4 + g;
                const int o0 = __shfl_sync(0xffffffffu, b0, src) + fe;
                const int o1 = __shfl_sync(0xffffffffu, b1, src) + fe;
                const int o2 = __shfl_sync(0xffffffffu, b2, src) + fe;
                a[k] = *(const ulonglong2*)&g_tp[0][o0];
                b[k] = *(const ulonglong2*)&g_tp[1][o1];
                c[k] = *(const ulonglong2*)&g_tp[2][o2];
                ob[k] = (long long)(base + src) * FEAT + fe;
            }
            // Multiply + dual streaming stores.
            #pragma unroll
            for (int k = 0; k < 4; k++) {
                ulonglong2 rr;
                rr.x = mul2(mul2(a[k].x, b[k].x), c[k].x);
                rr.y = mul2(mul2(a[k].y, b[k].y), c[k].y);
                const float4 r = *(float4*)&rr;
                __stcs((float4*)&out[ob[k]], r);        // feature_A
                __stcs((float4*)&out[nb + ob[k]], r);   // feature_B
            }
        }
    } else {
        // ---- Tail path: guarded per quad ----
        #pragma unroll
        for (int j = 0; j < PPW / 4; j++) {
            const int src = j * 4 + g;
            const int i = base + src;
            const int o0 = __shfl_sync(0xffffffffu, b0, src) + fe;
            const int o1 = __shfl_sync(0xffffffffu, b1, src) + fe;
            const int o2 = __shfl_sync(0xffffffffu, b2, src) + fe;
            if (i < n_main) {
                const ulonglong2 a = *(const ulonglong2*)&g_tp[0][o0];
                const ulonglong2 b = *(const ulonglong2*)&g_tp[1][o1];
                const ulonglong2 c = *(const ulonglong2*)&g_tp[2][o2];
                ulonglong2 rr;
                rr.x = mul2(mul2(a.x, b.x), c.x);
                rr.y = mul2(mul2(a.y, b.y), c.y);
                const float4 r = *(float4*)&rr;
                __stcs((float4*)&out[(long long)i * FEAT + fe], r);
                __stcs((float4*)&out[nb + (long long)i * FEAT + fe], r);
            }
        }
    }
}

extern "C" void kernel_launch(void* const* d_in, const int* in_sizes, int n_in,
                              void* d_out, int out_size) {
    const float* pts    = (const float*)d_in[0];
    const float* tim    = (const float*)d_in[1];
    const float* plane0 = (const float*)d_in[2];
    const float* plane1 = (const float*)d_in[3];
    const float* plane2 = (const float*)d_in[4];
    float* out = (float*)d_out;

    const int n = in_sizes[0] / 3;   // pts is [N,3]

    // 1) Transpose planes into [H,W,F] scratch.
    dim3 tg(HW / 256, 3);
    transpose_planes<<<tg, 256>>>(plane0, plane1, plane2);

    // 2) Main gather-product-store (fixup fused): 32 points per warp.
    const int block = 256;                         // 8 warps
    const int pts_per_block = (block / 32) * PPW;  // 256
    const int grid = (n + pts_per_block - 1) / pts_per_block;
    displacement_kernel<<<grid, block>>>(pts, tim, out, n);
}

// round 9
// speedup vs baseline: 1.0354x; 1.0354x over previous
#include <cuda_runtime.h>

#define FEAT 32
#define RES_H 512
#define RES_W 128
#define HW (RES_H * RES_W)
#define PLANE_ELEMS (FEAT * HW)
#define TIME_STEP_F 0.00390625f   /* 1/(2*128), exact in fp32 */
#define INV_BOUNDS_F 0.625f       /* fp32(1/fp32(1.6)) == 0.625 exactly (XLA folds /1.6 -> *0.625) */
#define PPW 32                    /* points per warp */

// 3 transposed planes, layout [H][W][F]: 32 features contiguous (one 128B line).
__device__ __align__(256) float g_tp[3][PLANE_ELEMS];

// Packed f32 pair multiply (sm_103a) — IEEE rn per element, bit-identical to
// two scalar __fmul_rn.
__device__ __forceinline__ unsigned long long mul2(unsigned long long a,
                                                   unsigned long long b) {
    unsigned long long r;
    asm("mul.rn.f32x2 %0, %1, %2;" : "=l"(r) : "l"(a), "l"(b));
    return r;
}

// L2-only 16B gather (bypass L1: gathers never hit L1 here, so skip fills).
__device__ __forceinline__ ulonglong2 ldcg2(const float* p) {
    ulonglong2 v;
    asm("ld.global.cg.v2.u64 {%0, %1}, [%2];"
        : "=l"(v.x), "=l"(v.y) : "l"(p));
    return v;
}

// ---------------------------------------------------------------------------
// Pre-pass: transpose [F=32, HW] -> [HW, F]. 256 hw x 32 f tiles, float4 both
// global sides, MLP=8.
// ---------------------------------------------------------------------------
__global__ void transpose_planes(const float* __restrict__ p0,
                                 const float* __restrict__ p1,
                                 const float* __restrict__ p2) {
    __shared__ float tile[256][33];
    const int plane = blockIdx.y;
    const float* __restrict__ src = (plane == 0) ? p0 : ((plane == 1) ? p1 : p2);
    float* __restrict__ dst = g_tp[plane];

    const int hw0 = blockIdx.x * 256;
    const int tid = threadIdx.x;

    #pragma unroll
    for (int k = 0; k < 8; k++) {
        const int lin = tid + 256 * k;
        const int f  = lin >> 6;
        const int vc = lin & 63;
        const float4 v = *(const float4*)&src[f * HW + hw0 + vc * 4];
        tile[vc * 4 + 0][f] = v.x;
        tile[vc * 4 + 1][f] = v.y;
        tile[vc * 4 + 2][f] = v.z;
        tile[vc * 4 + 3][f] = v.w;
    }
    __syncthreads();
    #pragma unroll
    for (int k = 0; k < 8; k++) {
        const int lin = tid + 256 * k;
        const int r  = lin >> 3;
        const int fc = lin & 7;
        float4 w;
        w.x = tile[r][fc * 4 + 0];
        w.y = tile[r][fc * 4 + 1];
        w.z = tile[r][fc * 4 + 2];
        w.w = tile[r][fc * 4 + 3];
        *(float4*)&dst[(hw0 + r) * FEAT + fc * 4] = w;
    }
}

// ---------------------------------------------------------------------------
// Index math — XLA-folded forms, round half-to-even, clamp. No FMA contraction.
// ---------------------------------------------------------------------------
__device__ __forceinline__ int idx_w(float c) {
    float v = __fmul_rn(__fadd_rn(c, 1.0f), 63.5f);     // 0.5*(128-1) folded
    int k = (int)rintf(v);
    return min(max(k, 0), RES_W - 1);
}
__device__ __forceinline__ int idx_h(float c) {
    float v = __fmul_rn(__fadd_rn(c, 1.0f), 255.5f);    // 0.5*(512-1) folded
    int k = (int)rintf(v);
    return min(max(k, 0), RES_H - 1);
}

// ---------------------------------------------------------------------------
// Main kernel: warp handles PPW=32 points.
// Phase 1: every lane computes the 3 plane base offsets of one point.
// Phase 2: 8 quad-iterations (g=lane>>3 -> point, lane&7 -> float4 chunk):
//   3 shfl + 3 L2-only LDG.128 + packed muls + 2 streaming STG.128.
//   Point n-1 handled by warp 0's fused fixup (disjoint rows -> race-free).
// ---------------------------------------------------------------------------
__global__ void __launch_bounds__(256, 6)
displacement_kernel(const float* __restrict__ pts,
                    const float* __restrict__ tim,
                    float* __restrict__ out,
                    int n) {
    const int warp_id = blockIdx.x * (blockDim.x >> 5) + (threadIdx.x >> 5);
    const int lane = threadIdx.x & 31;
    const long long nb = (long long)n * FEAT;

    // ---- Fused last-point fixup (warp 0 only; writes rows for i = n-1) ----
    if (warp_id == 0) {
        const int i = n - 1;
        const float t  = __fadd_rn(__fmul_rn(tim[i], 2.0f), -1.0f);
        const float p0 = __fmul_rn(-pts[3 * i + 0], INV_BOUNDS_F);
        const float p1 = __fmul_rn(-pts[3 * i + 1], INV_BOUNDS_F);
        const float p2 = __fmul_rn(-pts[3 * i + 2], INV_BOUNDS_F);
        const int ix = idx_w(t);
        const float fo = __fmul_rn(__fmul_rn(
            __ldg(&g_tp[0][(idx_h(p0) * RES_W + ix) * FEAT + lane]),
            __ldg(&g_tp[1][(idx_h(p1) * RES_W + ix) * FEAT + lane])),
            __ldg(&g_tp[2][(idx_h(p2) * RES_W + ix) * FEAT + lane]));
        // data.at[-1].add(-TIME_STEP): all 4 coords of the last row shift.
        const float ts = __fadd_rn(t,  -TIME_STEP_F);
        const float q0 = __fadd_rn(p0, -TIME_STEP_F);
        const float q1 = __fadd_rn(p1, -TIME_STEP_F);
        const float q2 = __fadd_rn(p2, -TIME_STEP_F);
        const int ixs = idx_w(ts);
        const float fs = __fmul_rn(__fmul_rn(
            __ldg(&g_tp[0][(idx_h(q0) * RES_W + ixs) * FEAT + lane]),
            __ldg(&g_tp[1][(idx_h(q1) * RES_W + ixs) * FEAT + lane])),
            __ldg(&g_tp[2][(idx_h(q2) * RES_W + ixs) * FEAT + lane]));
        const bool cond = __fadd_rn(p0, TIME_STEP_F) > 1.0f;
        out[(long long)i * FEAT + lane]      = cond ? fs : fo;   // feature_A
        out[nb + (long long)i * FEAT + lane] = cond ? fo : fs;   // feature_B
    }

    const int base = warp_id * PPW;
    if (base >= n) return;

    // Phase 1: one point per lane.
    int b0 = 0, b1 = 0, b2 = 0;
    const int li = base + lane;
    if (li < n) {
        const float t  = __fadd_rn(__fmul_rn(tim[li], 2.0f), -1.0f);
        const float p0 = __fmul_rn(-pts[3 * li + 0], INV_BOUNDS_F);
        const float p1 = __fmul_rn(-pts[3 * li + 1], INV_BOUNDS_F);
        const float p2 = __fmul_rn(-pts[3 * li + 2], INV_BOUNDS_F);
        const int ix = idx_w(t);
        b0 = (idx_h(p0) * RES_W + ix) * FEAT;
        b1 = (idx_h(p1) * RES_W + ix) * FEAT;
        b2 = (idx_h(p2) * RES_W + ix) * FEAT;
    }

    const int g  = lane >> 3;          // point within quad
    const int fe = (lane & 7) * 4;     // feature chunk
    const int n_main = n - 1;          // point n-1 handled by fixup

    if (base + PPW <= n_main) {
        // ---- Fast path: unguarded quads ----
        #pragma unroll
        for (int j = 0; j < PPW / 4; j++) {
            const int src = j * 4 + g;
            const int i = base + src;
            const int o0 = __shfl_sync(0xffffffffu, b0, src) + fe;
            const int o1 = __shfl_sync(0xffffffffu, b1, src) + fe;
            const int o2 = __shfl_sync(0xffffffffu, b2, src) + fe;
            const ulonglong2 a = ldcg2(&g_tp[0][o0]);
            const ulonglong2 b = ldcg2(&g_tp[1][o1]);
            const ulonglong2 c = ldcg2(&g_tp[2][o2]);
            ulonglong2 rr;
            rr.x = mul2(mul2(a.x, b.x), c.x);
            rr.y = mul2(mul2(a.y, b.y), c.y);
            const float4 r = *(float4*)&rr;
            __stcs((float4*)&out[(long long)i * FEAT + fe], r);        // A
            __stcs((float4*)&out[nb + (long long)i * FEAT + fe], r);   // B
        }
    } else {
        // ---- Tail path: guarded per quad ----
        #pragma unroll
        for (int j = 0; j < PPW / 4; j++) {
            const int src = j * 4 + g;
            const int i = base + src;
            const int o0 = __shfl_sync(0xffffffffu, b0, src) + fe;
            const int o1 = __shfl_sync(0xffffffffu, b1, src) + fe;
            const int o2 = __shfl_sync(0xffffffffu, b2, src) + fe;
            if (i < n_main) {
                const ulonglong2 a = ldcg2(&g_tp[0][o0]);
                const ulonglong2 b = ldcg2(&g_tp[1][o1]);
                const ulonglong2 c = ldcg2(&g_tp[2][o2]);
                ulonglong2 rr;
                rr.x = mul2(mul2(a.x, b.x), c.x);
                rr.y = mul2(mul2(a.y, b.y), c.y);
                const float4 r = *(float4*)&rr;
                __stcs((float4*)&out[(long long)i * FEAT + fe], r);
                __stcs((float4*)&out[nb + (long long)i * FEAT + fe], r);
            }
        }
    }
}

extern "C" void kernel_launch(void* const* d_in, const int* in_sizes, int n_in,
                              void* d_out, int out_size) {
    const float* pts    = (const float*)d_in[0];
    const float* tim    = (const float*)d_in[1];
    const float* plane0 = (const float*)d_in[2];
    const float* plane1 = (const float*)d_in[3];
    const float* plane2 = (const float*)d_in[4];
    float* out = (float*)d_out;

    const int n = in_sizes[0] / 3;   // pts is [N,3]

    // 1) Transpose planes into [H,W,F] scratch.
    dim3 tg(HW / 256, 3);
    transpose_planes<<<tg, 256>>>(plane0, plane1, plane2);

    // 2) Main gather-product-store (fixup fused): 32 points per warp.
    const int block = 256;                         // 8 warps
    const int pts_per_block = (block / 32) * PPW;  // 256
    const int grid = (n + pts_per_block - 1) / pts_per_block;
    displacement_kernel<<<grid, block>>>(pts, tim, out, n);
}